// round 3
// baseline (speedup 1.0000x reference)
#include <cuda_runtime.h>

#define D 12
#define KMAX 512
#define THREADS 128
#define TPT 4
#define TOK_PER_BLK (THREADS * TPT)

typedef unsigned long long u64;

// smem layout (dynamic): s_cb[512][12] float2 (broadcast-packed {w,w}),
// then s_w2[512] float2 ({w2,w2}), then s_red[THREADS] float.
#define SMEM_CB_BYTES  (KMAX * D * 8)          // 49152
#define SMEM_W2_BYTES  (KMAX * 8)              // 4096
#define SMEM_BYTES     (SMEM_CB_BYTES + SMEM_W2_BYTES + THREADS * 4)

__device__ float g_partial[1024];

__device__ __forceinline__ u64 pack2(float a, float b) {
    u64 r; asm("mov.b64 %0, {%1, %2};" : "=l"(r) : "f"(a), "f"(b)); return r;
}
__device__ __forceinline__ void unpack2(u64 v, float &a, float &b) {
    asm("mov.b64 {%0, %1}, %2;" : "=f"(a), "=f"(b) : "l"(v));
}
__device__ __forceinline__ u64 fma2(u64 a, u64 b, u64 c) {
    u64 r; asm("fma.rn.f32x2 %0, %1, %2, %3;" : "=l"(r) : "l"(a), "l"(b), "l"(c)); return r;
}
__device__ __forceinline__ u64 mul2(u64 a, u64 b) {
    u64 r; asm("mul.rn.f32x2 %0, %1, %2;" : "=l"(r) : "l"(a), "l"(b)); return r;
}
__device__ __forceinline__ u64 add2(u64 a, u64 b) {
    u64 r; asm("add.rn.f32x2 %0, %1, %2;" : "=l"(r) : "l"(a), "l"(b)); return r;
}

__global__ void __launch_bounds__(THREADS)
vq_kernel(const float* __restrict__ x, const float* __restrict__ cb,
          int tokens, int K,
          float* __restrict__ q_out, float* __restrict__ idx_out,
          int do_loss)
{
    extern __shared__ char smem_raw[];
    float2 (*s_cb)[D] = (float2(*)[D])smem_raw;                    // {w,w} pairs
    float2* s_w2 = (float2*)(smem_raw + SMEM_CB_BYTES);            // {w2,w2}
    float*  s_red = (float*)(smem_raw + SMEM_CB_BYTES + SMEM_W2_BYTES);

    // ---- Stage codebook: broadcast-packed {w,w} ----
    for (int i = threadIdx.x; i < K * D; i += THREADS) {
        const float v = cb[i];
        ((float2*)&s_cb[0][0])[i] = make_float2(v, v);
    }
    __syncthreads();
    // w2_k: sequential fp32 fma chain d = 0..11 (emulates reference sum order)
    for (int k = threadIdx.x; k < K; k += THREADS) {
        float s = 0.f;
        #pragma unroll
        for (int d = 0; d < D; d++) {
            const float w = s_cb[k][d].x;
            s = fmaf(w, w, s);
        }
        s_w2[k] = make_float2(s, s);
    }
    __syncthreads();

    // ---- Load 4 tokens, compute x2 (sequential fma chain), pack token-pairs ----
    const int base = blockIdx.x * TOK_PER_BLK + threadIdx.x;
    float xv[TPT][D];
    float x2s[TPT];
    bool  valid[TPT];
    #pragma unroll
    for (int i = 0; i < TPT; i++) {
        const int t = base + i * THREADS;
        valid[i] = (t < tokens);
        if (valid[i]) {
            const float4* xp4 = (const float4*)(x + (size_t)t * D);
            float4 a = xp4[0], b = xp4[1], c = xp4[2];
            xv[i][0]=a.x; xv[i][1]=a.y; xv[i][2]=a.z; xv[i][3]=a.w;
            xv[i][4]=b.x; xv[i][5]=b.y; xv[i][6]=b.z; xv[i][7]=b.w;
            xv[i][8]=c.x; xv[i][9]=c.y; xv[i][10]=c.z; xv[i][11]=c.w;
        } else {
            #pragma unroll
            for (int d = 0; d < D; d++) xv[i][d] = 0.f;
        }
        float s = 0.f;
        #pragma unroll
        for (int d = 0; d < D; d++) s = fmaf(xv[i][d], xv[i][d], s);
        x2s[i] = s;
    }

    // Token-pair packing: pair p holds tokens (2p, 2p+1) in lanes {lo, hi}.
    u64 xp[TPT / 2][D];
    u64 x2p[TPT / 2];
    #pragma unroll
    for (int p = 0; p < TPT / 2; p++) {
        #pragma unroll
        for (int d = 0; d < D; d++) xp[p][d] = pack2(xv[2*p][d], xv[2*p+1][d]);
        x2p[p] = pack2(x2s[2*p], x2s[2*p+1]);
    }

    float best[TPT];
    int   bi[TPT];
    #pragma unroll
    for (int i = 0; i < TPT; i++) { best[i] = 3.4e38f; bi[i] = 0; }

    const u64 NEG1 = pack2(-1.0f, -1.0f);
    const u64* cb64 = (const u64*)&s_cb[0][0];
    const u64* w264 = (const u64*)s_w2;

    // ---- Bit-faithful distance: fl(fl(x2 - fl(2*xw)) + w2), xw = seq fma chain ----
    #pragma unroll 1
    for (int k = 0; k < K; k++) {
        u64 c[D];
        #pragma unroll
        for (int d = 0; d < D; d++) c[d] = cb64[k * D + d];
        const u64 w2 = w264[k];

        #pragma unroll
        for (int p = 0; p < TPT / 2; p++) {
            u64 acc = mul2(xp[p][0], c[0]);              // == fma(x0,w0,0)
            #pragma unroll
            for (int d = 1; d < D; d++) acc = fma2(xp[p][d], c[d], acc);
            const u64 t2 = add2(acc, acc);               // 2*xw, exact
            const u64 u  = fma2(t2, NEG1, x2p[p]);       // fl(x2 - 2*xw)
            const u64 v  = add2(u, w2);                  // fl(u + w2)
            float v0, v1;
            unpack2(v, v0, v1);
            if (v0 < best[2*p])   { best[2*p]   = v0; bi[2*p]   = k; }
            if (v1 < best[2*p+1]) { best[2*p+1] = v1; bi[2*p+1] = k; }
        }
    }

    // ---- Emit: qst = fl(x + fl(q - x)) (straight-through), indices, loss ----
    float lsum = 0.f;
    #pragma unroll
    for (int i = 0; i < TPT; i++) {
        if (!valid[i]) continue;
        const int t = base + i * THREADS;
        float q[D], d1[D], qst[D];
        #pragma unroll
        for (int d = 0; d < D; d++) q[d] = s_cb[bi[i]][d].x;
        #pragma unroll
        for (int d = 0; d < D; d++) {
            d1[d]  = q[d] - xv[i][d];      // fl(q - x)
            qst[d] = xv[i][d] + d1[d];     // fl(x + (q - x))
            lsum = fmaf(d1[d], d1[d], lsum);
        }
        if (q_out) {
            float4* o = (float4*)(q_out + (size_t)t * D);
            o[0] = make_float4(qst[0], qst[1], qst[2],  qst[3]);
            o[1] = make_float4(qst[4], qst[5], qst[6],  qst[7]);
            o[2] = make_float4(qst[8], qst[9], qst[10], qst[11]);
        }
        if (idx_out) idx_out[t] = (float)bi[i];
    }

    if (do_loss) {
        s_red[threadIdx.x] = lsum;
        __syncthreads();
        #pragma unroll
        for (int s = THREADS / 2; s > 0; s >>= 1) {
            if (threadIdx.x < s) s_red[threadIdx.x] += s_red[threadIdx.x + s];
            __syncthreads();
        }
        if (threadIdx.x == 0) g_partial[blockIdx.x] = s_red[0];
    }
}

__global__ void __launch_bounds__(256)
vq_finalize(int nblocks, int tokens, float* __restrict__ loss_out)
{
    __shared__ float s[256];
    float v = 0.f;
    for (int i = threadIdx.x; i < nblocks; i += 256) v += g_partial[i];
    s[threadIdx.x] = v;
    __syncthreads();
    #pragma unroll
    for (int st = 128; st > 0; st >>= 1) {
        if (threadIdx.x < st) s[threadIdx.x] += s[threadIdx.x + st];
        __syncthreads();
    }
    if (threadIdx.x == 0) {
        const float m = s[0] / ((float)tokens * 12.0f);
        loss_out[0] = m + 0.25f * m;   // codebook_loss + commitment_loss
    }
}

extern "C" void kernel_launch(void* const* d_in, const int* in_sizes, int n_in,
                              void* d_out, int out_size)
{
    const float* x;
    const float* cb;
    int xs, cs;
    if (in_sizes[0] >= in_sizes[1]) {
        x = (const float*)d_in[0]; cb = (const float*)d_in[1];
        xs = in_sizes[0]; cs = in_sizes[1];
    } else {
        x = (const float*)d_in[1]; cb = (const float*)d_in[0];
        xs = in_sizes[1]; cs = in_sizes[0];
    }
    const int tokens = xs / D;
    int K = cs / D;
    if (K > KMAX) K = KMAX;

    float* out = (float*)d_out;
    const long long QN = (long long)tokens * D;

    float* q_out    = nullptr;
    float* idx_out  = nullptr;
    float* loss_out = nullptr;
    if ((long long)out_size == (long long)tokens) {
        idx_out = out;
    } else {
        q_out = out;
        if ((long long)out_size >= QN + tokens)     idx_out  = out + QN;
        if ((long long)out_size >= QN + tokens + 1) loss_out = out + QN + tokens;
        else if ((long long)out_size == QN + 1)     loss_out = out + QN;
    }

    static bool attr_set = false;
    if (!attr_set) {
        cudaFuncSetAttribute(vq_kernel,
                             cudaFuncAttributeMaxDynamicSharedMemorySize,
                             SMEM_BYTES);
        attr_set = true;
    }

    int grid = (tokens + TOK_PER_BLK - 1) / TOK_PER_BLK;
    if (grid > 1024) grid = 1024;

    vq_kernel<<<grid, THREADS, SMEM_BYTES>>>(x, cb, tokens, K, q_out, idx_out,
                                             loss_out != nullptr ? 1 : 0);
    if (loss_out)
        vq_finalize<<<1, 256>>>(grid, tokens, loss_out);
}

// round 4
// speedup vs baseline: 1.3337x; 1.3337x over previous
#include <cuda_runtime.h>

#define D 12
#define KMAX 512
#define THREADS 128
#define TPT 2
#define TOK_PER_BLK (THREADS * TPT)   // 256

typedef unsigned long long u64;

__device__ float        g_partial[1024];
__device__ unsigned int g_ctr = 0;

__device__ __forceinline__ u64 pack2(float a, float b) {
    u64 r; asm("mov.b64 %0, {%1, %2};" : "=l"(r) : "f"(a), "f"(b)); return r;
}
__device__ __forceinline__ void unpack2(u64 v, float &a, float &b) {
    asm("mov.b64 {%0, %1}, %2;" : "=f"(a), "=f"(b) : "l"(v));
}
__device__ __forceinline__ u64 fma2(u64 a, u64 b, u64 c) {
    u64 r; asm("fma.rn.f32x2 %0, %1, %2, %3;" : "=l"(r) : "l"(a), "l"(b), "l"(c)); return r;
}
__device__ __forceinline__ u64 mul2(u64 a, u64 b) {
    u64 r; asm("mul.rn.f32x2 %0, %1, %2;" : "=l"(r) : "l"(a), "l"(b)); return r;
}
__device__ __forceinline__ u64 add2(u64 a, u64 b) {
    u64 r; asm("add.rn.f32x2 %0, %1, %2;" : "=l"(r) : "l"(a), "l"(b)); return r;
}

__global__ void __launch_bounds__(THREADS, 4)
vq_kernel(const float* __restrict__ x, const float* __restrict__ cb,
          int tokens, int K,
          float* __restrict__ q_out, float* __restrict__ idx_out,
          float* __restrict__ loss_out)
{
    // Code-pair packed codebook: s_cb[j][d] = {cb[2j][d], cb[2j+1][d]}
    __shared__ __align__(16) u64 s_cb[KMAX / 2][D];   // 24576 B
    __shared__ u64   s_w2[KMAX / 2];                  // {w2[2j], w2[2j+1]}, 2048 B
    __shared__ float s_red[THREADS];
    __shared__ int   s_last;

    const int tid = threadIdx.x;
    const int K2 = K >> 1;

    // ---- Load this thread's 2 tokens first (overlap with smem staging) ----
    const int t0 = blockIdx.x * TOK_PER_BLK + tid;
    const int t1 = t0 + THREADS;
    float xv0[D], xv1[D];
    const bool v0ok = (t0 < tokens), v1ok = (t1 < tokens);
    {
        float4 a = {0,0,0,0}, b = {0,0,0,0}, c = {0,0,0,0};
        if (v0ok) { const float4* p = (const float4*)(x + (size_t)t0 * D); a=p[0]; b=p[1]; c=p[2]; }
        xv0[0]=a.x; xv0[1]=a.y; xv0[2]=a.z; xv0[3]=a.w;
        xv0[4]=b.x; xv0[5]=b.y; xv0[6]=b.z; xv0[7]=b.w;
        xv0[8]=c.x; xv0[9]=c.y; xv0[10]=c.z; xv0[11]=c.w;
    }
    {
        float4 a = {0,0,0,0}, b = {0,0,0,0}, c = {0,0,0,0};
        if (v1ok) { const float4* p = (const float4*)(x + (size_t)t1 * D); a=p[0]; b=p[1]; c=p[2]; }
        xv1[0]=a.x; xv1[1]=a.y; xv1[2]=a.z; xv1[3]=a.w;
        xv1[4]=b.x; xv1[5]=b.y; xv1[6]=b.z; xv1[7]=b.w;
        xv1[8]=c.x; xv1[9]=c.y; xv1[10]=c.z; xv1[11]=c.w;
    }

    // ---- Stage codebook into code-pair packed shared (coalesced gmem reads) ----
    {
        float* s_cb_f = (float*)&s_cb[0][0];
        for (int i = tid; i < K * D; i += THREADS) {
            const int k = i / D, d = i - k * D;
            // float slot: pair j = k>>1, lane = k&1 -> offset j*24 + d*2 + lane (floats)
            s_cb_f[(k >> 1) * (2 * D) + d * 2 + (k & 1)] = cb[i];
        }
    }
    __syncthreads();
    // w2 per code: sequential fp32 fma chain d = 0..11 (bit-faithful)
    {
        float* s_w2_f = (float*)s_w2;
        const float* s_cb_f = (const float*)&s_cb[0][0];
        for (int k = tid; k < K; k += THREADS) {
            const int j = k >> 1, lane = k & 1;
            float s = 0.f;
            #pragma unroll
            for (int d = 0; d < D; d++) {
                const float w = s_cb_f[j * (2 * D) + d * 2 + lane];
                s = fmaf(w, w, s);
            }
            s_w2_f[j * 2 + lane] = s;
        }
    }
    __syncthreads();

    // ---- x2 (sequential chain) and broadcast-pair registers ----
    float x2s0 = 0.f, x2s1 = 0.f;
    #pragma unroll
    for (int d = 0; d < D; d++) x2s0 = fmaf(xv0[d], xv0[d], x2s0);
    #pragma unroll
    for (int d = 0; d < D; d++) x2s1 = fmaf(xv1[d], xv1[d], x2s1);

    u64 xb0[D], xb1[D];
    #pragma unroll
    for (int d = 0; d < D; d++) { xb0[d] = pack2(xv0[d], xv0[d]); xb1[d] = pack2(xv1[d], xv1[d]); }
    const u64 x2b0 = pack2(x2s0, x2s0);
    const u64 x2b1 = pack2(x2s1, x2s1);
    const u64 NEG2 = pack2(-2.0f, -2.0f);

    float best0 = 3.4e38f, best1 = 3.4e38f;
    int   bi0 = 0, bi1 = 0;

    // ---- Main loop: 2 codes/iter x 2 tokens; lanes = codes (2j, 2j+1) ----
    #pragma unroll 1
    for (int j = 0; j < K2; j++) {
        const float4* row = (const float4*)&s_cb[j][0];
        const float4 f0 = row[0], f1 = row[1], f2 = row[2];
        const float4 f3 = row[3], f4 = row[4], f5 = row[5];
        u64 c[D];
        c[0]  = pack2(f0.x, f0.y); c[1]  = pack2(f0.z, f0.w);
        c[2]  = pack2(f1.x, f1.y); c[3]  = pack2(f1.z, f1.w);
        c[4]  = pack2(f2.x, f2.y); c[5]  = pack2(f2.z, f2.w);
        c[6]  = pack2(f3.x, f3.y); c[7]  = pack2(f3.z, f3.w);
        c[8]  = pack2(f4.x, f4.y); c[9]  = pack2(f4.z, f4.w);
        c[10] = pack2(f5.x, f5.y); c[11] = pack2(f5.z, f5.w);
        const u64 w2p = s_w2[j];

        // two interleaved dependent chains (one per token) for ILP
        u64 a0 = mul2(xb0[0], c[0]);
        u64 a1 = mul2(xb1[0], c[0]);
        #pragma unroll
        for (int d = 1; d < D; d++) {
            a0 = fma2(xb0[d], c[d], a0);
            a1 = fma2(xb1[d], c[d], a1);
        }
        // u = fl(x2 - 2*acc)  (== fl(x2 - fl(2*acc)) since 2*acc is exact)
        u64 r0 = fma2(a0, NEG2, x2b0);
        u64 r1 = fma2(a1, NEG2, x2b1);
        r0 = add2(r0, w2p);               // fl(u + w2)
        r1 = add2(r1, w2p);

        float d00, d01, d10, d11;
        unpack2(r0, d00, d01);
        unpack2(r1, d10, d11);
        // lane0 = code 2j (lower index) checked first -> first-min tiebreak
        if (d00 < best0) { best0 = d00; bi0 = 2 * j; }
        if (d01 < best0) { best0 = d01; bi0 = 2 * j + 1; }
        if (d10 < best1) { best1 = d10; bi1 = 2 * j; }
        if (d11 < best1) { best1 = d11; bi1 = 2 * j + 1; }
    }

    // ---- Emit qst = fl(x + fl(q - x)), indices, loss partials ----
    const float* s_cb_f = (const float*)&s_cb[0][0];
    float lsum = 0.f;

    if (v0ok) {
        const int j = bi0 >> 1, lane = bi0 & 1;
        float qst[D];
        #pragma unroll
        for (int d = 0; d < D; d++) {
            const float q  = s_cb_f[j * (2 * D) + d * 2 + lane];
            const float d1 = q - xv0[d];
            qst[d] = xv0[d] + d1;
            lsum = fmaf(d1, d1, lsum);
        }
        if (q_out) {
            float4* o = (float4*)(q_out + (size_t)t0 * D);
            o[0] = make_float4(qst[0], qst[1], qst[2],  qst[3]);
            o[1] = make_float4(qst[4], qst[5], qst[6],  qst[7]);
            o[2] = make_float4(qst[8], qst[9], qst[10], qst[11]);
        }
        if (idx_out) idx_out[t0] = (float)bi0;
    }
    if (v1ok) {
        const int j = bi1 >> 1, lane = bi1 & 1;
        float qst[D];
        #pragma unroll
        for (int d = 0; d < D; d++) {
            const float q  = s_cb_f[j * (2 * D) + d * 2 + lane];
            const float d1 = q - xv1[d];
            qst[d] = xv1[d] + d1;
            lsum = fmaf(d1, d1, lsum);
        }
        if (q_out) {
            float4* o = (float4*)(q_out + (size_t)t1 * D);
            o[0] = make_float4(qst[0], qst[1], qst[2],  qst[3]);
            o[1] = make_float4(qst[4], qst[5], qst[6],  qst[7]);
            o[2] = make_float4(qst[8], qst[9], qst[10], qst[11]);
        }
        if (idx_out) idx_out[t1] = (float)bi1;
    }

    // ---- Loss: block reduce, then last-done block finalizes (no 2nd kernel) ----
    if (loss_out) {
        s_red[tid] = lsum;
        __syncthreads();
        #pragma unroll
        for (int s = THREADS / 2; s > 0; s >>= 1) {
            if (tid < s) s_red[tid] += s_red[tid + s];
            __syncthreads();
        }
        if (tid == 0) {
            g_partial[blockIdx.x] = s_red[0];
            __threadfence();
            // self-resetting counter: wraps to 0 after gridDim.x increments
            const unsigned old = atomicInc(&g_ctr, gridDim.x - 1);
            s_last = (old == gridDim.x - 1);
        }
        __syncthreads();
        if (s_last) {
            __threadfence();   // make all blocks' g_partial writes visible
            float v = 0.f;
            for (int i = tid; i < (int)gridDim.x; i += THREADS) v += g_partial[i];
            s_red[tid] = v;
            __syncthreads();
            #pragma unroll
            for (int s = THREADS / 2; s > 0; s >>= 1) {
                if (tid < s) s_red[tid] += s_red[tid + s];
                __syncthreads();
            }
            if (tid == 0) {
                const float m = s_red[0] / ((float)tokens * 12.0f);
                loss_out[0] = m + 0.25f * m;
            }
        }
    }
}

extern "C" void kernel_launch(void* const* d_in, const int* in_sizes, int n_in,
                              void* d_out, int out_size)
{
    const float* x;
    const float* cb;
    int xs, cs;
    if (in_sizes[0] >= in_sizes[1]) {
        x = (const float*)d_in[0]; cb = (const float*)d_in[1];
        xs = in_sizes[0]; cs = in_sizes[1];
    } else {
        x = (const float*)d_in[1]; cb = (const float*)d_in[0];
        xs = in_sizes[1]; cs = in_sizes[0];
    }
    const int tokens = xs / D;
    int K = cs / D;
    if (K > KMAX) K = KMAX;
    if (K & 1) K -= 1;   // pair loop requires even K (K=512 here)

    float* out = (float*)d_out;
    const long long QN = (long long)tokens * D;

    float* q_out    = nullptr;
    float* idx_out  = nullptr;
    float* loss_out = nullptr;
    if ((long long)out_size == (long long)tokens) {
        idx_out = out;
    } else {
        q_out = out;
        if ((long long)out_size >= QN + tokens)     idx_out  = out + QN;
        if ((long long)out_size >= QN + tokens + 1) loss_out = out + QN + tokens;
        else if ((long long)out_size == QN + 1)     loss_out = out + QN;
    }

    int grid = (tokens + TOK_PER_BLK - 1) / TOK_PER_BLK;   // 512 for this shape
    if (grid > 1024) grid = 1024;                           // g_partial capacity

    vq_kernel<<<grid, THREADS>>>(x, cb, tokens, K, q_out, idx_out, loss_out);
}

// round 5
// speedup vs baseline: 1.4097x; 1.0570x over previous
#include <cuda_runtime.h>

#define D 12
#define KMAX 512
#define THREADS 128
#define CAP_TOK 256            // max tokens a block can handle (128 thr x 2)
#define NSM 148

typedef unsigned long long u64;

__device__ float        g_partial[1024];
__device__ unsigned int g_ctr = 0;

__device__ __forceinline__ u64 pack2(float a, float b) {
    u64 r; asm("mov.b64 %0, {%1, %2};" : "=l"(r) : "f"(a), "f"(b)); return r;
}
__device__ __forceinline__ void unpack2(u64 v, float &a, float &b) {
    asm("mov.b64 {%0, %1}, %2;" : "=f"(a), "=f"(b) : "l"(v));
}
__device__ __forceinline__ u64 fma2(u64 a, u64 b, u64 c) {
    u64 r; asm("fma.rn.f32x2 %0, %1, %2, %3;" : "=l"(r) : "l"(a), "l"(b), "l"(c)); return r;
}
__device__ __forceinline__ u64 mul2(u64 a, u64 b) {
    u64 r; asm("mul.rn.f32x2 %0, %1, %2;" : "=l"(r) : "l"(a), "l"(b)); return r;
}
__device__ __forceinline__ u64 add2(u64 a, u64 b) {
    u64 r; asm("add.rn.f32x2 %0, %1, %2;" : "=l"(r) : "l"(a), "l"(b)); return r;
}

__global__ void __launch_bounds__(THREADS, 4)
vq_kernel(const float* __restrict__ x, const float* __restrict__ cb,
          int tokens, int K,
          float* __restrict__ q_out, float* __restrict__ idx_out,
          float* __restrict__ loss_out)
{
    // Code-pair packed codebook: s_cb[j][d] = {cb[2j][d], cb[2j+1][d]}
    __shared__ __align__(16) u64 s_cb[KMAX / 2][D];   // 24576 B
    __shared__ __align__(16) u64 s_w2[KMAX / 2];      // {w2[2j], w2[2j+1]}
    __shared__ float s_red[THREADS];
    __shared__ int   s_last;

    const int tid = threadIdx.x;
    const int K2 = K >> 1;

    // ---- Balanced token partition: all blocks co-resident, equal work ----
    const int start = (int)(((long long)blockIdx.x       * tokens) / gridDim.x);
    const int end   = (int)(((long long)(blockIdx.x + 1) * tokens) / gridDim.x);
    const int t0 = start + tid;
    const int t1 = start + tid + THREADS;
    const bool v0ok = (t0 < end), v1ok = (t1 < end);

    float xv0[D], xv1[D];
    {
        float4 a = {0,0,0,0}, b = {0,0,0,0}, c = {0,0,0,0};
        if (v0ok) { const float4* p = (const float4*)(x + (size_t)t0 * D); a=p[0]; b=p[1]; c=p[2]; }
        xv0[0]=a.x; xv0[1]=a.y; xv0[2]=a.z; xv0[3]=a.w;
        xv0[4]=b.x; xv0[5]=b.y; xv0[6]=b.z; xv0[7]=b.w;
        xv0[8]=c.x; xv0[9]=c.y; xv0[10]=c.z; xv0[11]=c.w;
    }
    {
        float4 a = {0,0,0,0}, b = {0,0,0,0}, c = {0,0,0,0};
        if (v1ok) { const float4* p = (const float4*)(x + (size_t)t1 * D); a=p[0]; b=p[1]; c=p[2]; }
        xv1[0]=a.x; xv1[1]=a.y; xv1[2]=a.z; xv1[3]=a.w;
        xv1[4]=b.x; xv1[5]=b.y; xv1[6]=b.z; xv1[7]=b.w;
        xv1[8]=c.x; xv1[9]=c.y; xv1[10]=c.z; xv1[11]=c.w;
    }

    // ---- Stage codebook code-pair packed ----
    {
        float* s_cb_f = (float*)&s_cb[0][0];
        for (int i = tid; i < K * D; i += THREADS) {
            const int k = i / D, d = i - k * D;
            s_cb_f[(k >> 1) * (2 * D) + d * 2 + (k & 1)] = cb[i];
        }
    }
    __syncthreads();
    // w2 per code: sequential fp32 fma chain (bit-faithful to reference)
    {
        float* s_w2_f = (float*)s_w2;
        const float* s_cb_f = (const float*)&s_cb[0][0];
        for (int k = tid; k < K; k += THREADS) {
            const int j = k >> 1, lane = k & 1;
            float s = 0.f;
            #pragma unroll
            for (int d = 0; d < D; d++) {
                const float w = s_cb_f[j * (2 * D) + d * 2 + lane];
                s = fmaf(w, w, s);
            }
            s_w2_f[j * 2 + lane] = s;
        }
    }
    __syncthreads();

    // ---- x2 (sequential chain), broadcast-pair registers ----
    float x2s0 = 0.f, x2s1 = 0.f;
    #pragma unroll
    for (int d = 0; d < D; d++) x2s0 = fmaf(xv0[d], xv0[d], x2s0);
    #pragma unroll
    for (int d = 0; d < D; d++) x2s1 = fmaf(xv1[d], xv1[d], x2s1);

    u64 xb0[D], xb1[D];
    #pragma unroll
    for (int d = 0; d < D; d++) { xb0[d] = pack2(xv0[d], xv0[d]); xb1[d] = pack2(xv1[d], xv1[d]); }
    const u64 x2b0 = pack2(x2s0, x2s0);
    const u64 x2b1 = pack2(x2s1, x2s1);
    const u64 NEG2 = pack2(-2.0f, -2.0f);

    float best0 = 3.4e38f, best1 = 3.4e38f;
    int   bi0 = 0, bi1 = 0;

    // ---- Main loop: 4 codes (2 pairs) x 2 tokens per iter ----
    #pragma unroll 1
    for (int j = 0; j < K2; j += 2) {
        const ulonglong2* rA = (const ulonglong2*)&s_cb[j][0];
        const ulonglong2* rB = (const ulonglong2*)&s_cb[j + 1][0];
        u64 cA[D], cB[D];
        #pragma unroll
        for (int h = 0; h < 6; h++) {
            const ulonglong2 a = rA[h]; cA[2*h] = a.x; cA[2*h+1] = a.y;
            const ulonglong2 b = rB[h]; cB[2*h] = b.x; cB[2*h+1] = b.y;
        }
        const ulonglong2 w2v = *(const ulonglong2*)&s_w2[j];
        const u64 w2A = w2v.x, w2B = w2v.y;

        // 4 independent fma chains (bit-exact sequential order per lane)
        u64 pA0 = mul2(xb0[0], cA[0]);
        u64 pA1 = mul2(xb1[0], cA[0]);
        u64 pB0 = mul2(xb0[0], cB[0]);
        u64 pB1 = mul2(xb1[0], cB[0]);
        #pragma unroll
        for (int d = 1; d < D; d++) {
            pA0 = fma2(xb0[d], cA[d], pA0);
            pA1 = fma2(xb1[d], cA[d], pA1);
            pB0 = fma2(xb0[d], cB[d], pB0);
            pB1 = fma2(xb1[d], cB[d], pB1);
        }
        const u64 rA0 = add2(fma2(pA0, NEG2, x2b0), w2A);
        const u64 rA1 = add2(fma2(pA1, NEG2, x2b1), w2A);
        const u64 rB0 = add2(fma2(pB0, NEG2, x2b0), w2B);
        const u64 rB1 = add2(fma2(pB1, NEG2, x2b1), w2B);

        const int kb = 2 * j;

        // token 0: candidates kb..kb+3 (branchless; first-min tiebreak)
        {
            float a0, a1, b0, b1;
            unpack2(rA0, a0, a1);
            unpack2(rB0, b0, b1);
            const float mA = fminf(a0, a1);
            const int   iA = (a1 < a0) ? (kb + 1) : kb;
            const float mB = fminf(b0, b1);
            const int   iB = (b1 < b0) ? (kb + 3) : (kb + 2);
            const float m  = fminf(mA, mB);
            const int   ci = (mB < mA) ? iB : iA;
            bi0   = (m < best0) ? ci : bi0;
            best0 = fminf(best0, m);
        }
        // token 1
        {
            float a0, a1, b0, b1;
            unpack2(rA1, a0, a1);
            unpack2(rB1, b0, b1);
            const float mA = fminf(a0, a1);
            const int   iA = (a1 < a0) ? (kb + 1) : kb;
            const float mB = fminf(b0, b1);
            const int   iB = (b1 < b0) ? (kb + 3) : (kb + 2);
            const float m  = fminf(mA, mB);
            const int   ci = (mB < mA) ? iB : iA;
            bi1   = (m < best1) ? ci : bi1;
            best1 = fminf(best1, m);
        }
    }

    // ---- Emit qst = fl(x + fl(q - x)), indices, loss partials ----
    const float* s_cb_f = (const float*)&s_cb[0][0];
    float lsum = 0.f;

    if (v0ok) {
        const int j = bi0 >> 1, lane = bi0 & 1;
        float qst[D];
        #pragma unroll
        for (int d = 0; d < D; d++) {
            const float q  = s_cb_f[j * (2 * D) + d * 2 + lane];
            const float d1 = q - xv0[d];
            qst[d] = xv0[d] + d1;
            lsum = fmaf(d1, d1, lsum);
        }
        if (q_out) {
            float4* o = (float4*)(q_out + (size_t)t0 * D);
            o[0] = make_float4(qst[0], qst[1], qst[2],  qst[3]);
            o[1] = make_float4(qst[4], qst[5], qst[6],  qst[7]);
            o[2] = make_float4(qst[8], qst[9], qst[10], qst[11]);
        }
        if (idx_out) idx_out[t0] = (float)bi0;
    }
    if (v1ok) {
        const int j = bi1 >> 1, lane = bi1 & 1;
        float qst[D];
        #pragma unroll
        for (int d = 0; d < D; d++) {
            const float q  = s_cb_f[j * (2 * D) + d * 2 + lane];
            const float d1 = q - xv1[d];
            qst[d] = xv1[d] + d1;
            lsum = fmaf(d1, d1, lsum);
        }
        if (q_out) {
            float4* o = (float4*)(q_out + (size_t)t1 * D);
            o[0] = make_float4(qst[0], qst[1], qst[2],  qst[3]);
            o[1] = make_float4(qst[4], qst[5], qst[6],  qst[7]);
            o[2] = make_float4(qst[8], qst[9], qst[10], qst[11]);
        }
        if (idx_out) idx_out[t1] = (float)bi1;
    }

    // ---- Loss: block reduce + last-block finalize (single kernel) ----
    if (loss_out) {
        s_red[tid] = lsum;
        __syncthreads();
        #pragma unroll
        for (int s = THREADS / 2; s > 0; s >>= 1) {
            if (tid < s) s_red[tid] += s_red[tid + s];
            __syncthreads();
        }
        if (tid == 0) {
            g_partial[blockIdx.x] = s_red[0];
            __threadfence();
            const unsigned old = atomicInc(&g_ctr, gridDim.x - 1);  // self-resets
            s_last = (old == gridDim.x - 1);
        }
        __syncthreads();
        if (s_last) {
            __threadfence();
            float v = 0.f;
            for (int i = tid; i < (int)gridDim.x; i += THREADS) v += g_partial[i];
            s_red[tid] = v;
            __syncthreads();
            #pragma unroll
            for (int s = THREADS / 2; s > 0; s >>= 1) {
                if (tid < s) s_red[tid] += s_red[tid + s];
                __syncthreads();
            }
            if (tid == 0) {
                const float m = s_red[0] / ((float)tokens * 12.0f);
                loss_out[0] = m + 0.25f * m;
            }
        }
    }
}

extern "C" void kernel_launch(void* const* d_in, const int* in_sizes, int n_in,
                              void* d_out, int out_size)
{
    const float* x;
    const float* cb;
    int xs, cs;
    if (in_sizes[0] >= in_sizes[1]) {
        x = (const float*)d_in[0]; cb = (const float*)d_in[1];
        xs = in_sizes[0]; cs = in_sizes[1];
    } else {
        x = (const float*)d_in[1]; cb = (const float*)d_in[0];
        xs = in_sizes[1]; cs = in_sizes[0];
    }
    const int tokens = xs / D;
    int K = cs / D;
    if (K > KMAX) K = KMAX;
    K &= ~3;   // loop processes 4 codes/iter (K=512 here)

    float* out = (float*)d_out;
    const long long QN = (long long)tokens * D;

    float* q_out    = nullptr;
    float* idx_out  = nullptr;
    float* loss_out = nullptr;
    if ((long long)out_size == (long long)tokens) {
        idx_out = out;
    } else {
        q_out = out;
        if ((long long)out_size >= QN + tokens)     idx_out  = out + QN;
        if ((long long)out_size >= QN + tokens + 1) loss_out = out + QN + tokens;
        else if ((long long)out_size == QN + 1)     loss_out = out + QN;
    }

    // Balanced single-wave grid: 4 blocks per SM, all co-resident.
    int need = (tokens + CAP_TOK - 1) / CAP_TOK;
    int grid = 4 * NSM;               // 592
    if (grid < need) grid = need;     // each block must fit in 256-token cap
    if (grid > 1024) grid = 1024;     // g_partial capacity

    vq_kernel<<<grid, THREADS>>>(x, cb, tokens, K, q_out, idx_out, loss_out);
}